// round 15
// baseline (speedup 1.0000x reference)
#include <cuda_runtime.h>
#include <cuda_bf16.h>

#define BN 8
#define MO 12
#define DD 512
#define NO 37
#define NA 6
#define NT 3
#define EM 128
#define NAA 100
#define NC 300
#define KK 72
#define PP 5112            // KK*(KK-1)
#define FD 1536
#define HF 768
#define FE (PP*NT)         // 15336 floats per batch per array
#define TPB 512

// fused grid: heads, pools, tabs, valid-pair, tail-fill
#define HEADB (BN*MO)              // 96
#define PPB   8
#define POOLB (BN*PPB)             // 64
#define TABB  4
#define VALB  BN                   // 8
#define TAILB BN                   // 8
#define GRID  (HEADB + POOLB + TABB + VALB + TAILB)   // 180

// output layout (flattened, tuple order)
#define OFF_FINAL 0
#define OFF_PL    (BN*NC)
#define OFF_TT    (OFF_PL + BN*PP*NT)
#define OFF_ACT   (OFF_TT + BN*PP*NT)
#define OFF_OBJ   (OFF_ACT + BN*MO*NA)

// ---------------- device scratch ----------------
__device__ int      g_sel6[BN*MO];
__device__ int      g_aaidx[BN*KK];
__device__ int      g_objidx[BN*MO];
__device__ float    g_inpdot[BN*MO*6];
__device__ float    g_objtab[NO*6];
__device__ float    g_acttab[NA*6];
__device__ float    g_nonexist[BN*NC];
__device__ float    g_invconst[NT];
__device__ int      g_headdone[BN];   // 12 each
__device__ int      g_pooldone[BN];   // 8 each
__device__ int      g_tabdone;        // 4
__device__ int      g_hcons[BN];      // 2 consumers each (valid b, tail b)
__device__ int      g_tcons;          // 16 consumers

__device__ __forceinline__ float warpsum(float v){
    #pragma unroll
    for(int o=16;o>0;o>>=1) v += __shfl_xor_sync(0xffffffffu, v, o);
    return v;
}
__device__ __forceinline__ unsigned fmap(float f){
    unsigned u=__float_as_uint(f);
    return (u & 0x80000000u) ? ~u : (u | 0x80000000u);
}
__device__ __forceinline__ float funmap(unsigned u){
    return __uint_as_float((u & 0x80000000u) ? (u ^ 0x80000000u) : ~u);
}
__device__ __forceinline__ float dot4(float4 a, float4 b){
    return a.x*b.x + a.y*b.y + a.z*b.z + a.w*b.w;
}
__device__ __forceinline__ int ldvol(int* p){ return *((volatile int*)p); }

__global__ __launch_bounds__(TPB) void
kFused(const float* __restrict__ inp, const float* __restrict__ objmask,
       const float* __restrict__ W_obj, const float* __restrict__ b_obj,
       const float* __restrict__ W_act, const float* __restrict__ b_act,
       const float* __restrict__ W_tr,  const float* __restrict__ b_tr,
       const float* __restrict__ W_ne,  const float* __restrict__ b_ne,
       const float* __restrict__ obj_emb, const float* __restrict__ act_emb,
       const int* __restrict__ AA, const float* __restrict__ TR,
       const int* __restrict__ lookup, float* __restrict__ out){
    int blk = blockIdx.x;
    int tid = threadIdx.x, w = tid>>5, lane = tid&31;

    if(blk < HEADB){
        // ========== head block (b,o): R9-proven + release-signal ==========
        __shared__ float4 row[DD/4];
        __shared__ float  res[NO+NA];
        int bo = blk, b = bo/MO, o = bo%MO;
        const float4* ir = (const float4*)(inp + (size_t)bo*DD);
        if(tid < DD/4) row[tid]=ir[tid];
        __syncthreads();
        for(int c=w; c<NO+NA+6; c+=16){
            const float4* W;
            if(c<NO)            W = (const float4*)(W_obj + (size_t)c*DD);
            else if(c<NO+NA)    W = (const float4*)(W_act + (size_t)(c-NO)*DD);
            else { int idx=c-NO-NA; int t=idx>>1, h=idx&1;
                   W = (const float4*)(W_tr + (size_t)t*FD + h*HF); }
            float acc=0.f;
            #pragma unroll
            for(int d=lane; d<DD/4; d+=32) acc += dot4(row[d], W[d]);
            acc = warpsum(acc);
            if(lane==0){
                if(c<NO){ float v=acc+b_obj[c]; res[c]=v; out[OFF_OBJ + bo*NO + c]=v; }
                else if(c<NO+NA){ float v=acc+b_act[c-NO]; res[c]=v; out[OFF_ACT + bo*NA + (c-NO)]=v; }
                else __stcg(&g_inpdot[bo*6 + (c-NO-NA)], acc);
            }
        }
        __syncthreads();
        if(tid==0){
            int best=0; float bv=res[0];
            #pragma unroll
            for(int c=1;c<NO;c++) if(res[c]>bv){ bv=res[c]; best=c; }
            __stcg(&g_objidx[bo], best);
        }
        if(w==0){
            bool s=false;
            if(lane < NA){
                int k = o*NA + lane;
                bool act_on = (res[NO+lane] > 0.0f) && (objmask[bo] == 1.0f);
                int  aa = AA[b*KK + k];
                s = act_on && (aa != -1);
                __stcg(&g_aaidx[b*KK+k], s ? aa : -1);
            }
            unsigned m = __ballot_sync(0xffffffffu, s);
            if(lane==0) __stcg(&g_sel6[bo], (int)(m & 0x3fu));
        }
        __threadfence();
        __syncthreads();
        if(tid==0) atomicAdd(&g_headdone[b], 1);
    } else if(blk < HEADB + POOLB){
        // ========== pool block (R9-proven) + release-signal ==========
        int bb = blk - HEADB;
        int b = bb/PPB, part = bb%PPB;
        __shared__ float4 pooled[DD/4];
        __shared__ float  msum_s;
        if(tid==0){
            float m=0.f;
            for(int o=0;o<MO;o++) m += objmask[b*MO+o];
            msum_s=m;
        }
        __syncthreads();
        float inv = 1.0f/msum_s;
        if(tid < DD/4){
            float4 s = make_float4(0,0,0,0);
            #pragma unroll
            for(int o=0;o<MO;o++){
                float m = objmask[b*MO+o];
                float4 v = ((const float4*)(inp + ((size_t)b*MO+o)*DD))[tid];
                s.x += v.x*m; s.y += v.y*m; s.z += v.z*m; s.w += v.w*m;
            }
            pooled[tid] = make_float4(s.x*inv, s.y*inv, s.z*inv, s.w*inv);
        }
        __syncthreads();
        int c0 = part*38, c1 = c0+38; if(c1>NC) c1=NC;
        for(int c=c0+w; c<c1; c+=16){
            const float4* W = (const float4*)(W_ne + (size_t)c*DD);
            float acc=0.f;
            #pragma unroll
            for(int d=lane; d<DD/4; d+=32) acc += dot4(pooled[d], W[d]);
            acc = warpsum(acc);
            if(lane==0) __stcg(&g_nonexist[b*NC+c], acc + b_ne[c]);
        }
        __threadfence();
        __syncthreads();
        if(tid==0) atomicAdd(&g_pooldone[b], 1);
    } else if(blk < HEADB + POOLB + TABB){
        // ========== tab block (R9-proven) + release-signal ==========
        int gw = (blk - HEADB - POOLB)*16 + w;      // 0..63
        for(int c=gw; c<NO*6 + NA*6 + NT; c+=64){
            if(c < NO*6 + NA*6){
                const float* src; const float* Wv;
                if(c < NO*6){
                    int oi=c/6, idx=c%6, t=idx>>1, h=idx&1;
                    src = obj_emb + (size_t)oi*EM;
                    Wv  = W_tr + (size_t)t*FD + h*HF + DD;
                } else {
                    int cc=c-NO*6; int a=cc/6, idx=cc%6, t=idx>>1, h=idx&1;
                    src = act_emb + (size_t)a*EM;
                    Wv  = W_tr + (size_t)t*FD + h*HF + DD + EM;
                }
                float4 a4 = ((const float4*)src)[lane];
                float4 b4 = ((const float4*)Wv)[lane];
                float acc = warpsum(dot4(a4,b4));
                if(lane==0){
                    if(c < NO*6) __stcg(&g_objtab[c], acc);
                    else         __stcg(&g_acttab[c-NO*6], acc);
                }
            } else {
                int t = c - NO*6 - NA*6;
                const float4* W = (const float4*)(W_tr + (size_t)t*FD);
                float acc=0.f;
                #pragma unroll
                for(int d=lane; d<FD/4; d+=32) acc += W[d].x+W[d].y+W[d].z+W[d].w;
                acc = warpsum(acc);
                if(lane==0) __stcg(&g_invconst[t], b_tr[t] - acc);
            }
        }
        __threadfence();
        __syncthreads();
        if(tid==0) atomicAdd(&g_tabdone, 1);
    } else if(blk < HEADB + POOLB + TABB + VALB){
        // ========== valid-pair block for batch b (R14 role-0, lean) ==========
        int b = blk - HEADB - POOLB - TABB;
        __shared__ float s1s[KK*NT], s2s[KK*NT], btr[NT];
        __shared__ int   aas[KK], sel6s[MO];
        __shared__ short cps[KK+1];
        __shared__ unsigned char listS[KK];
        __shared__ unsigned segS[NC];
        __shared__ float nexS[NC];

        if(tid < NT) btr[tid] = b_tr[tid];
        if(tid < NC) segS[tid] = 0u;
        if(tid==0){
            while(ldvol(&g_headdone[b]) < MO) { }
            while(ldvol(&g_tabdone) < TABB) { }
            while(ldvol(&g_pooldone[b]) < PPB) { }
        }
        __syncthreads();
        __threadfence();

        if(tid < MO) sel6s[tid] = __ldcg(&g_sel6[b*MO+tid]);
        if(tid < KK){
            int k=tid, o=k/NA, a=k%NA;
            int oi = __ldcg(&g_objidx[b*MO+o]);
            aas[k] = __ldcg(&g_aaidx[b*KK+k]);
            #pragma unroll
            for(int t=0;t<NT;t++){
                s1s[k*NT+t] = __ldcg(&g_inpdot[(b*MO+o)*6 + t*2+0]) + __ldcg(&g_objtab[oi*6 + t*2+0]) + __ldcg(&g_acttab[a*6 + t*2+0]);
                s2s[k*NT+t] = __ldcg(&g_inpdot[(b*MO+o)*6 + t*2+1]) + __ldcg(&g_objtab[oi*6 + t*2+1]) + __ldcg(&g_acttab[a*6 + t*2+1]);
            }
        }
        if(tid < NC) nexS[tid] = __ldcg(&g_nonexist[b*NC+tid]);
        __syncthreads();
        // consume-reset (2 consumers of headdone/tabdone; sole consumer of pooldone)
        if(tid==0){
            *((volatile int*)&g_pooldone[b]) = 0;
            int oh = atomicAdd(&g_hcons[b], 1);
            if(oh == 1){ *((volatile int*)&g_headdone[b]) = 0; *((volatile int*)&g_hcons[b]) = 0; }
            int ot = atomicAdd(&g_tcons, 1);
            if(ot == 2*BN-1){ *((volatile int*)&g_tabdone) = 0; *((volatile int*)&g_tcons) = 0; }
        }
        if(tid <= KK){
            int full = tid/NA, rem = tid%NA, c = 0;
            for(int o=0;o<full;o++) c += __popc(sel6s[o]);
            if(tid < KK) c += __popc(sel6s[full] & ((1<<rem)-1));
            cps[tid] = (short)c;
        }
        __syncthreads();
        if(tid < KK){
            if((sel6s[tid/NA]>>(tid%NA)) & 1) listS[cps[tid]] = (unsigned char)tid;
        }
        __syncthreads();

        int S   = cps[KK];
        int SM1 = S-1;
        int SS1 = S*SM1;
        float invS = (S>1) ? 1.0f/(float)SM1 : 0.f;
        float* plb = out + OFF_PL + (size_t)b*FE;
        float* ttb = out + OFF_TT + (size_t)b*FE;

        for(int q=tid; q<SS1; q+=TPB){
            int a_ = (int)((float)q * invS);
            if(a_ > 0 && a_*SM1 > q) a_--;
            if((a_+1)*SM1 <= q) a_++;
            int r_ = q - a_*SM1;
            int i = listS[a_];
            int j = listS[r_ < a_ ? r_ : r_+1];
            const float* trp = TR + (((size_t)b*KK + i)*KK + j)*NT;
            const int*   lk  = lookup + ((size_t)aas[i]*NAA + aas[j])*NT;
            float l0 = s1s[i*NT+0] + s2s[j*NT+0] + btr[0];
            float l1 = s1s[i*NT+1] + s2s[j*NT+1] + btr[1];
            float l2 = s1s[i*NT+2] + s2s[j*NT+2] + btr[2];
            plb[q*3+0]=l0; plb[q*3+1]=l1; plb[q*3+2]=l2;
            ttb[q*3+0]=__ldg(trp); ttb[q*3+1]=__ldg(trp+1); ttb[q*3+2]=__ldg(trp+2);
            atomicMax(&segS[lk[0]], fmap(l0));
            atomicMax(&segS[lk[1]], fmap(l1));
            atomicMax(&segS[lk[2]], fmap(l2));
        }

        __syncthreads();
        if(tid < NC){
            unsigned u = segS[tid];
            out[OFF_FINAL + b*NC + tid] = u ? funmap(u) : nexS[tid];
        }
    } else {
        // ========== tail-fill block for batch b (R14 role-1) ==========
        int b = blk - HEADB - POOLB - TABB - VALB;
        __shared__ int   Ssh;
        __shared__ float invcS[NT];
        if(tid==0){
            while(ldvol(&g_headdone[b]) < MO) { }
            while(ldvol(&g_tabdone) < TABB) { }
        }
        __syncthreads();
        __threadfence();
        if(tid < NT) invcS[tid] = __ldcg(&g_invconst[tid]);
        if(tid == 0){
            int S=0;
            #pragma unroll
            for(int o=0;o<MO;o++) S += __popc((unsigned)__ldcg(&g_sel6[b*MO+o]));
            Ssh = S;
        }
        __syncthreads();
        if(tid==0){
            int oh = atomicAdd(&g_hcons[b], 1);
            if(oh == 1){ *((volatile int*)&g_headdone[b]) = 0; *((volatile int*)&g_hcons[b]) = 0; }
            int ot = atomicAdd(&g_tcons, 1);
            if(ot == 2*BN-1){ *((volatile int*)&g_tabdone) = 0; *((volatile int*)&g_tcons) = 0; }
        }
        int S  = Ssh;
        int vB = S*(S-1)*NT;                        // first invalid float index
        float* plb = out + OFF_PL + (size_t)b*FE;
        float* ttb = out + OFF_TT + (size_t)b*FE;
        int start4 = (vB+3) & ~3;
        if(tid < start4 - vB){
            plb[vB+tid] = invcS[(vB+tid)%3];
            ttb[vB+tid] = -1.0f;
        }
        float4 pat[3];
        #pragma unroll
        for(int m=0;m<3;m++)
            pat[m] = make_float4(invcS[(4*m+0)%3], invcS[(4*m+1)%3],
                                 invcS[(4*m+2)%3], invcS[(4*m+3)%3]);
        const float4 neg1 = make_float4(-1.f,-1.f,-1.f,-1.f);
        float4* pl4 = (float4*)plb;
        float4* tt4 = (float4*)ttb;
        for(int v = start4/4 + tid; v < FE/4; v += TPB){
            pl4[v] = pat[v%3];
            tt4[v] = neg1;
        }
    }
}

extern "C" void kernel_launch(void* const* d_in, const int* in_sizes, int n_in,
                              void* d_out, int out_size){
    const float* inp     = (const float*)d_in[0];
    const float* objmask = (const float*)d_in[1];
    const float* TR      = (const float*)d_in[2];
    const float* W_obj   = (const float*)d_in[3];
    const float* b_obj   = (const float*)d_in[4];
    const float* W_act   = (const float*)d_in[5];
    const float* b_act   = (const float*)d_in[6];
    const float* W_tr    = (const float*)d_in[7];
    const float* b_tr    = (const float*)d_in[8];
    const float* W_ne    = (const float*)d_in[9];
    const float* b_ne    = (const float*)d_in[10];
    const float* obj_emb = (const float*)d_in[11];
    const float* act_emb = (const float*)d_in[12];
    const int*   AA      = (const int*)d_in[13];
    const int*   lookup  = (const int*)d_in[15];
    float* out = (float*)d_out;

    kFused<<<GRID, TPB>>>(inp, objmask, W_obj, b_obj, W_act, b_act,
                          W_tr, b_tr, W_ne, b_ne, obj_emb, act_emb,
                          AA, TR, lookup, out);
}

// round 16
// speedup vs baseline: 1.0842x; 1.0842x over previous
#include <cuda_runtime.h>
#include <cuda_bf16.h>

#define BN 8
#define MO 12
#define DD 512
#define NO 37
#define NA 6
#define NT 3
#define EM 128
#define NAA 100
#define NC 300
#define KK 72
#define PP 5112            // KK*(KK-1)
#define FD 1536
#define HF 768
#define FE (PP*NT)         // 15336 floats per batch per array
#define NDOT (NO+NA+6)     // 49

// kA grid layout (R14 proven)
#define HEADB (BN*MO)      // 96
#define PPB   8
#define POOLB (BN*PPB)     // 64
#define TABB  4
#define KA_GRID (HEADB + POOLB + TABB)   // 164

// kC grid: 8 valid-pair blocks + 8 tail-fill blocks (R14 proven)
#define KC_GRID (2*BN)     // 16

// output layout (flattened, tuple order)
#define OFF_FINAL 0
#define OFF_PL    (BN*NC)
#define OFF_TT    (OFF_PL + BN*PP*NT)
#define OFF_ACT   (OFF_TT + BN*PP*NT)
#define OFF_OBJ   (OFF_ACT + BN*MO*NA)

// ---------------- device scratch ----------------
__device__ int      g_sel6[BN*MO];
__device__ int      g_aaidx[BN*KK];
__device__ int      g_objidx[BN*MO];
__device__ float    g_inpdot[BN*MO*6];
__device__ float    g_objtab[NO*6];
__device__ float    g_acttab[NA*6];
__device__ float    g_nonexist[BN*NC];
__device__ float    g_invconst[NT];

__device__ __forceinline__ float warpsum(float v){
    #pragma unroll
    for(int o=16;o>0;o>>=1) v += __shfl_xor_sync(0xffffffffu, v, o);
    return v;
}
__device__ __forceinline__ unsigned fmap(float f){
    unsigned u=__float_as_uint(f);
    return (u & 0x80000000u) ? ~u : (u | 0x80000000u);
}
__device__ __forceinline__ float funmap(unsigned u){
    return __uint_as_float((u & 0x80000000u) ? (u ^ 0x80000000u) : ~u);
}
__device__ __forceinline__ float dot4(float4 a, float4 b){
    return a.x*b.x + a.y*b.y + a.z*b.z + a.w*b.w;
}

// ================ kA: heads + pool + tables — concurrent-accumulator dots ================
__global__ __launch_bounds__(512) void
kA(const float* __restrict__ inp, const float* __restrict__ objmask,
   const float* __restrict__ W_obj, const float* __restrict__ b_obj,
   const float* __restrict__ W_act, const float* __restrict__ b_act,
   const float* __restrict__ W_tr,  const float* __restrict__ b_tr,
   const float* __restrict__ W_ne,  const float* __restrict__ b_ne,
   const float* __restrict__ obj_emb, const float* __restrict__ act_emb,
   const int* __restrict__ AA, float* __restrict__ out){
    int blk = blockIdx.x;
    int tid = threadIdx.x, w = tid>>5, lane = tid&31;

    if(blk < HEADB){
        // ---- heads: 49 dot-512, one d-pass, <=4 concurrent accumulators/warp ----
        __shared__ float4 row[DD/4];
        __shared__ float  res[NO+NA];
        int bo = blk, b = bo/MO, o = bo%MO;
        const float4* ir = (const float4*)(inp + (size_t)bo*DD);
        if(tid < DD/4) row[tid]=ir[tid];
        __syncthreads();
        int nd=0; int cs[4]; const float4* Wp[4];
        for(int c=w; c<NDOT; c+=16){
            cs[nd]=c;
            if(c<NO)          Wp[nd] = (const float4*)(W_obj + (size_t)c*DD);
            else if(c<NO+NA)  Wp[nd] = (const float4*)(W_act + (size_t)(c-NO)*DD);
            else { int idx=c-NO-NA; int t=idx>>1, h=idx&1;
                   Wp[nd] = (const float4*)(W_tr + (size_t)t*FD + h*HF); }
            nd++;
        }
        float acc[4]={0.f,0.f,0.f,0.f};
        #pragma unroll 4
        for(int d=lane; d<DD/4; d+=32){
            float4 r = row[d];
            #pragma unroll
            for(int s=0;s<4;s++) if(s<nd) acc[s] += dot4(r, Wp[s][d]);
        }
        #pragma unroll
        for(int s=0;s<4;s++) if(s<nd){
            float v = warpsum(acc[s]);
            if(lane==0){
                int c = cs[s];
                if(c<NO){ float x=v+b_obj[c]; res[c]=x; out[OFF_OBJ + bo*NO + c]=x; }
                else if(c<NO+NA){ float x=v+b_act[c-NO]; res[c]=x; out[OFF_ACT + bo*NA + (c-NO)]=x; }
                else g_inpdot[bo*6 + (c-NO-NA)] = v;
            }
        }
        __syncthreads();
        if(tid==0){
            int best=0; float bv=res[0];
            #pragma unroll
            for(int c=1;c<NO;c++) if(res[c]>bv){ bv=res[c]; best=c; }
            g_objidx[bo]=best;
        }
        if(w==0){
            bool s=false;
            if(lane < NA){
                int k = o*NA + lane;
                bool act_on = (res[NO+lane] > 0.0f) && (objmask[bo] == 1.0f);
                int  aa = AA[b*KK + k];
                s = act_on && (aa != -1);
                g_aaidx[b*KK+k] = s ? aa : -1;
            }
            unsigned m = __ballot_sync(0xffffffffu, s);
            if(lane==0) g_sel6[bo] = (int)(m & 0x3fu);
        }
    } else if(blk < HEADB + POOLB){
        // ---- pool: 38 dot-512, one d-pass, <=3 concurrent accumulators/warp ----
        int bb = blk - HEADB;
        int b = bb/PPB, part = bb%PPB;
        __shared__ float4 pooled[DD/4];
        __shared__ float  msum_s;
        if(tid==0){
            float m=0.f;
            for(int o=0;o<MO;o++) m += objmask[b*MO+o];
            msum_s=m;
        }
        __syncthreads();
        float inv = 1.0f/msum_s;
        if(tid < DD/4){
            float4 s = make_float4(0,0,0,0);
            #pragma unroll
            for(int o=0;o<MO;o++){
                float m = objmask[b*MO+o];
                float4 v = ((const float4*)(inp + ((size_t)b*MO+o)*DD))[tid];
                s.x += v.x*m; s.y += v.y*m; s.z += v.z*m; s.w += v.w*m;
            }
            pooled[tid] = make_float4(s.x*inv, s.y*inv, s.z*inv, s.w*inv);
        }
        __syncthreads();
        int c0 = part*38, c1 = c0+38; if(c1>NC) c1=NC;
        int nd=0; int cs[3]; const float4* Wp[3];
        for(int c=c0+w; c<c1; c+=16){ cs[nd]=c; Wp[nd]=(const float4*)(W_ne + (size_t)c*DD); nd++; }
        float acc[3]={0.f,0.f,0.f};
        #pragma unroll 4
        for(int d=lane; d<DD/4; d+=32){
            float4 r = pooled[d];
            #pragma unroll
            for(int s=0;s<3;s++) if(s<nd) acc[s] += dot4(r, Wp[s][d]);
        }
        #pragma unroll
        for(int s=0;s<3;s++) if(s<nd){
            float v = warpsum(acc[s]);
            if(lane==0) g_nonexist[b*NC+cs[s]] = v + b_ne[cs[s]];
        }
    } else {
        int gw = (blk - HEADB - POOLB)*16 + w;      // 0..63
        for(int c=gw; c<NO*6 + NA*6 + NT; c+=64){
            if(c < NO*6 + NA*6){
                const float* src; const float* Wv;
                if(c < NO*6){
                    int oi=c/6, idx=c%6, t=idx>>1, h=idx&1;
                    src = obj_emb + (size_t)oi*EM;
                    Wv  = W_tr + (size_t)t*FD + h*HF + DD;
                } else {
                    int cc=c-NO*6; int a=cc/6, idx=cc%6, t=idx>>1, h=idx&1;
                    src = act_emb + (size_t)a*EM;
                    Wv  = W_tr + (size_t)t*FD + h*HF + DD + EM;
                }
                float4 a4 = ((const float4*)src)[lane];
                float4 b4 = ((const float4*)Wv)[lane];
                float acc = warpsum(dot4(a4,b4));
                if(lane==0){
                    if(c < NO*6) g_objtab[c] = acc;
                    else         g_acttab[c-NO*6] = acc;
                }
            } else {
                int t = c - NO*6 - NA*6;
                const float4* W = (const float4*)(W_tr + (size_t)t*FD);
                float acc=0.f;
                #pragma unroll
                for(int d=lane; d<FD/4; d+=32) acc += W[d].x+W[d].y+W[d].z+W[d].w;
                acc = warpsum(acc);
                if(lane==0) g_invconst[t] = b_tr[t] - acc;
            }
        }
    }
}

// ================ kC: blocks 0-7 valid pairs, blocks 8-15 tail fill (verbatim R14) ================
__global__ __launch_bounds__(1024) void
kC(const float* __restrict__ TR, const float* __restrict__ b_tr,
   const int* __restrict__ lookup, float* __restrict__ out){
    int b   = blockIdx.x & (BN-1);
    int role= blockIdx.x >> 3;
    int tid = threadIdx.x;

    if(role == 0){
        __shared__ float s1s[KK*NT], s2s[KK*NT], btr[NT];
        __shared__ int   aas[KK], sel6s[MO];
        __shared__ short cps[KK+1];
        __shared__ unsigned char listS[KK];
        __shared__ unsigned segS[NC];
        __shared__ float nexS[NC];

        if(tid < MO) sel6s[tid] = g_sel6[b*MO+tid];
        if(tid < KK){
            int k=tid, o=k/NA, a=k%NA;
            int oi = g_objidx[b*MO+o];
            aas[k] = g_aaidx[b*KK+k];
            #pragma unroll
            for(int t=0;t<NT;t++){
                s1s[k*NT+t] = g_inpdot[(b*MO+o)*6 + t*2+0] + g_objtab[oi*6 + t*2+0] + g_acttab[a*6 + t*2+0];
                s2s[k*NT+t] = g_inpdot[(b*MO+o)*6 + t*2+1] + g_objtab[oi*6 + t*2+1] + g_acttab[a*6 + t*2+1];
            }
        }
        if(tid < NT) btr[tid] = b_tr[tid];
        if(tid < NC){ segS[tid]=0u; nexS[tid]=g_nonexist[b*NC+tid]; }
        __syncthreads();
        if(tid <= KK){
            int full = tid/NA, rem = tid%NA, c = 0;
            for(int o=0;o<full;o++) c += __popc(sel6s[o]);
            if(tid < KK) c += __popc(sel6s[full] & ((1<<rem)-1));
            cps[tid] = (short)c;
        }
        __syncthreads();
        if(tid < KK){
            if((sel6s[tid/NA]>>(tid%NA)) & 1) listS[cps[tid]] = (unsigned char)tid;
        }
        __syncthreads();

        int S   = cps[KK];
        int SM1 = S-1;
        int SS1 = S*SM1;
        float invS = (S>1) ? 1.0f/(float)SM1 : 0.f;
        float* plb = out + OFF_PL + (size_t)b*FE;
        float* ttb = out + OFF_TT + (size_t)b*FE;

        for(int q=tid; q<SS1; q+=1024){
            int a_ = (int)((float)q * invS);
            if(a_ > 0 && a_*SM1 > q) a_--;
            if((a_+1)*SM1 <= q) a_++;
            int r_ = q - a_*SM1;
            int i = listS[a_];
            int j = listS[r_ < a_ ? r_ : r_+1];
            const float* trp = TR + (((size_t)b*KK + i)*KK + j)*NT;
            const int*   lk  = lookup + ((size_t)aas[i]*NAA + aas[j])*NT;
            float l0 = s1s[i*NT+0] + s2s[j*NT+0] + btr[0];
            float l1 = s1s[i*NT+1] + s2s[j*NT+1] + btr[1];
            float l2 = s1s[i*NT+2] + s2s[j*NT+2] + btr[2];
            plb[q*3+0]=l0; plb[q*3+1]=l1; plb[q*3+2]=l2;
            ttb[q*3+0]=__ldg(trp); ttb[q*3+1]=__ldg(trp+1); ttb[q*3+2]=__ldg(trp+2);
            atomicMax(&segS[lk[0]], fmap(l0));
            atomicMax(&segS[lk[1]], fmap(l1));
            atomicMax(&segS[lk[2]], fmap(l2));
        }

        __syncthreads();
        if(tid < NC){
            unsigned u = segS[tid];
            out[OFF_FINAL + b*NC + tid] = u ? funmap(u) : nexS[tid];
        }
    } else {
        __shared__ int   Ssh;
        __shared__ float invcS[NT];
        if(tid < NT) invcS[tid] = g_invconst[tid];
        if(tid == 0){
            int S=0;
            #pragma unroll
            for(int o=0;o<MO;o++) S += __popc((unsigned)g_sel6[b*MO+o]);
            Ssh = S;
        }
        __syncthreads();
        int S  = Ssh;
        int vB = S*(S-1)*NT;
        float* plb = out + OFF_PL + (size_t)b*FE;
        float* ttb = out + OFF_TT + (size_t)b*FE;
        int start4 = (vB+3) & ~3;
        if(tid < start4 - vB){
            plb[vB+tid] = invcS[(vB+tid)%3];
            ttb[vB+tid] = -1.0f;
        }
        float4 pat[3];
        #pragma unroll
        for(int m=0;m<3;m++)
            pat[m] = make_float4(invcS[(4*m+0)%3], invcS[(4*m+1)%3],
                                 invcS[(4*m+2)%3], invcS[(4*m+3)%3]);
        const float4 neg1 = make_float4(-1.f,-1.f,-1.f,-1.f);
        float4* pl4 = (float4*)plb;
        float4* tt4 = (float4*)ttb;
        for(int v = start4/4 + tid; v < FE/4; v += 1024){
            pl4[v] = pat[v%3];
            tt4[v] = neg1;
        }
    }
}

extern "C" void kernel_launch(void* const* d_in, const int* in_sizes, int n_in,
                              void* d_out, int out_size){
    const float* inp     = (const float*)d_in[0];
    const float* objmask = (const float*)d_in[1];
    const float* TR      = (const float*)d_in[2];
    const float* W_obj   = (const float*)d_in[3];
    const float* b_obj   = (const float*)d_in[4];
    const float* W_act   = (const float*)d_in[5];
    const float* b_act   = (const float*)d_in[6];
    const float* W_tr    = (const float*)d_in[7];
    const float* b_tr    = (const float*)d_in[8];
    const float* W_ne    = (const float*)d_in[9];
    const float* b_ne    = (const float*)d_in[10];
    const float* obj_emb = (const float*)d_in[11];
    const float* act_emb = (const float*)d_in[12];
    const int*   AA      = (const int*)d_in[13];
    const int*   lookup  = (const int*)d_in[15];
    float* out = (float*)d_out;

    kA<<<KA_GRID, 512>>>(inp, objmask, W_obj, b_obj, W_act, b_act,
                         W_tr, b_tr, W_ne, b_ne, obj_emb, act_emb, AA, out);
    kC<<<KC_GRID, 1024>>>(TR, b_tr, lookup, out);
}